// round 5
// baseline (speedup 1.0000x reference)
#include <cuda_runtime.h>
#include <cstdint>

#define B_  512
#define T_  512
#define F_  128
#define NU  50
#define NC  150   // 3*NU
#define XP  160   // padded X row (floats)

// Scratch for projected inputs X[b][t][160] (cols 150..159 unused garbage).
__device__ float g_X[(size_t)B_ * T_ * XP];

typedef unsigned long long ull;

// ---------------- packed f32x2 helpers ----------------
__device__ __forceinline__ ull dup2(float x) {
    ull r;
    asm("mov.b64 %0, {%1, %1};" : "=l"(r) : "f"(x));
    return r;
}
__device__ __forceinline__ void fma2(ull& d, ull a, ull b) {
    asm("fma.rn.f32x2 %0, %1, %2, %0;" : "+l"(d) : "l"(a), "l"(b));
}
__device__ __forceinline__ void unpack2(ull v, float& lo, float& hi) {
    asm("mov.b64 {%0, %1}, %2;" : "=f"(lo), "=f"(hi) : "l"(v));
}

__device__ __forceinline__ float sigm(float x) {
    return __fdividef(1.f, 1.f + __expf(-x));
}
__device__ __forceinline__ float tanh_fast(float x) {
    return __fdividef(2.f, 1.f + __expf(-2.f * x)) - 1.f;
}

__device__ __forceinline__ uint32_t smem_u32(const void* p) {
    uint32_t a;
    asm("{ .reg .u64 t; cvta.to.shared.u64 t, %1; cvt.u32.u64 %0, t; }"
        : "=r"(a) : "l"(p));
    return a;
}

// ---------------- Kernel 1: input projection (unchanged, best known) --------
#define RT    128            // rows (timesteps) per tile
#define AS    129            // odd stride for transposed A (conflict-free STS)
#define SM_W  (F_ * XP)      // 20480 floats
#define SM_B  (XP)           // 160
#define SM_A  (F_ * AS)      // 16512
#define SMEM_XPROJ ((SM_W + SM_B + SM_A) * 4)   // ~148.6 KB

__global__ void __launch_bounds__(512, 1) xproj_kernel(
    const float* __restrict__ inp, const float* __restrict__ W,
    const float* __restrict__ bb, const float* __restrict__ dp)
{
    extern __shared__ float sm[];
    float* Weff = sm;              // [128][160]
    float* bi_s = sm + SM_W;       // [160]
    float* A_s  = bi_s + SM_B;     // [128][129]  (k-major, transposed tile)

    const int b   = blockIdx.x;
    const int tid = threadIdx.x;

    for (int idx = tid; idx < F_ * XP; idx += 512) {
        int k = idx / XP, c = idx - k * XP;
        float w = 0.f;
        if (c < NC) w = W[k * NC + c] * dp[(c / NU) * (B_ * F_) + b * F_ + k];
        Weff[idx] = w;
    }
    for (int c = tid; c < XP; c += 512)
        bi_s[c] = (c < NC) ? bb[c] : 0.f;

    const int cx = tid & 15;
    const int ry = tid >> 4;
    const int r0 = ry * 4;
    const ull* Wv = reinterpret_cast<const ull*>(Weff);
    const ull* bv = reinterpret_cast<const ull*>(bi_s);

    for (int tile = 0; tile < T_ / RT; ++tile) {
        const int t0 = tile * RT;
        __syncthreads();
        const float* src = inp + ((size_t)b * T_ + t0) * F_;
        for (int idx = tid; idx < RT * F_; idx += 512) {
            int r = idx >> 7, k = idx & 127;
            A_s[k * AS + r] = src[idx];
        }
        __syncthreads();

        ull acc[4][5];
        #pragma unroll
        for (int i = 0; i < 4; ++i)
            #pragma unroll
            for (int j = 0; j < 5; ++j)
                acc[i][j] = bv[j * 16 + cx];

        #pragma unroll 2
        for (int k = 0; k < F_; ++k) {
            ull w[5];
            #pragma unroll
            for (int j = 0; j < 5; ++j)
                w[j] = Wv[k * (XP / 2) + j * 16 + cx];
            #pragma unroll
            for (int i = 0; i < 4; ++i) {
                ull ad = dup2(A_s[k * AS + r0 + i]);
                #pragma unroll
                for (int j = 0; j < 5; ++j)
                    fma2(acc[i][j], ad, w[j]);
            }
        }

        #pragma unroll
        for (int i = 0; i < 4; ++i) {
            ull* Xr = reinterpret_cast<ull*>(g_X + ((size_t)b * T_ + t0 + r0 + i) * XP);
            #pragma unroll
            for (int j = 0; j < 5; ++j)
                Xr[j * 16 + cx] = acc[i][j];
        }
    }
}

// ---------------- Kernel 2: recurrent scan (512 threads, 8-way split-K) -----
// 128 CTAs x 4 rows, 512 threads: u = tid&63, s = tid>>6 in 0..7 (j-octant).
// Splits s<4 also finalize row s. U in registers (21 ull), rows packed 2x2
// in fma2, smem float4 exchange (NO shuffles), 2 barriers/step.
// X staged via cp.async double buffer.
#define NSPL 8
#define JSEG 7
#define JPAD 56                       // 8*JSEG; j in [50,56) stays zero
#define CH   8                        // steps per chunk
#define XQ   38                       // float4 per (row,step)
#define XROWF4 (CH * XQ + 2)          // +32B pad per row
#define CHUNK_F4 (4 * CH * XQ)        // 1216

__global__ void __launch_bounds__(512, 1) scan_kernel(
    const float* __restrict__ U, const float* __restrict__ bb,
    const float* __restrict__ Wd, const float* __restrict__ bd,
    const float* __restrict__ rdp, float* __restrict__ out)
{
    __shared__ float4 hm[3][JPAD];          // [gate][j] = {h0m,h1m,h2m,h3m}
    __shared__ float4 part[NSPL][4][64];    // [split][row][u] = {z,r,h,_}
    __shared__ float4 Xs[2 * 4 * XROWF4];
    __shared__ float  head[4][64];

    const int tid = threadIdx.x;
    const int u   = tid & 63;              // unit (active if < 50)
    const int s   = tid >> 6;              // j-octant; s<4 also owns row s
    const int b0  = blockIdx.x * 4;
    const bool active = (u < NU);
    const bool fin    = (s < 4) && active; // finalizer for row s
    const int jbeg = s * JSEG;

    for (int idx = tid; idx < 3 * JPAD; idx += 512)
        (&hm[0][0])[idx] = make_float4(0.f, 0.f, 0.f, 0.f);

    // U slice in registers, duplicated for 2-row-packed fma2
    ull Uzd[JSEG], Urd[JSEG], Uhd[JSEG];
    #pragma unroll
    for (int jj = 0; jj < JSEG; ++jj) {
        int j = jbeg + jj;
        float vz = 0.f, vr = 0.f, vh = 0.f;
        if (active && j < NU) {
            vz = U[j * NC + u];
            vr = U[j * NC + NU + u];
            vh = U[j * NC + 2 * NU + u];
        }
        Uzd[jj] = dup2(vz); Urd[jj] = dup2(vr); Uhd[jj] = dup2(vh);
    }

    float br0 = 0.f, br1 = 0.f, br2 = 0.f, wdu = 0.f;
    float rdp0 = 0.f, rdp1 = 0.f, rdp2 = 0.f, h = 0.f;
    if (fin) {
        br0 = bb[NC + u]; br1 = bb[NC + NU + u]; br2 = bb[NC + 2 * NU + u];
        wdu = Wd[u];
        rdp0 = rdp[0 * (B_ * NU) + (b0 + s) * NU + u];
        rdp1 = rdp[1 * (B_ * NU) + (b0 + s) * NU + u];
        rdp2 = rdp[2 * (B_ * NU) + (b0 + s) * NU + u];
    }

    // ---- cp.async chunk loader (all 512 threads) ----
    const uint32_t xs_base = smem_u32(&Xs[0]);
    auto issue_chunk = [&](int c, int buf) {
        #pragma unroll
        for (int it = 0; it < 3; ++it) {
            int lin = it * 512 + tid;
            if (lin < CHUNK_F4) {
                int r   = lin / (CH * XQ);
                int rem = lin - r * (CH * XQ);
                int tt  = rem / XQ;
                int q   = rem - tt * XQ;
                const float* g = g_X + ((size_t)(b0 + r) * T_ + c * CH + tt) * XP + q * 4;
                uint32_t dst = xs_base +
                    (uint32_t)((buf * 4 + r) * XROWF4 + tt * XQ + q) * 16u;
                asm volatile("cp.async.cg.shared.global [%0], [%1], 16;"
                             :: "r"(dst), "l"(g) : "memory");
            }
        }
        asm volatile("cp.async.commit_group;" ::: "memory");
    };

    issue_chunk(0, 0);
    issue_chunk(1, 1);
    asm volatile("cp.async.wait_group 1;" ::: "memory");   // chunk 0 ready
    __syncthreads();

    const float* XrowBase = reinterpret_cast<const float*>(Xs);
    const int NCHUNK = T_ / CH;   // 64
    for (int c = 0; c < NCHUNK; ++c) {
        const int buf = c & 1;
        const float* Xrow = XrowBase + (size_t)(buf * 4 + s) * (XROWF4 * 4);

        #pragma unroll 2
        for (int tt = 0; tt < CH; ++tt) {
            // phase A: split-K partials for all 4 rows (2x2 packed)
            ull aZ0 = 0, aZ1 = 0, aR0 = 0, aR1 = 0, aH0 = 0, aH1 = 0;
            const ulonglong2* hz = reinterpret_cast<const ulonglong2*>(&hm[0][jbeg]);
            const ulonglong2* hr = reinterpret_cast<const ulonglong2*>(&hm[1][jbeg]);
            const ulonglong2* hh = reinterpret_cast<const ulonglong2*>(&hm[2][jbeg]);
            #pragma unroll
            for (int jj = 0; jj < JSEG; ++jj) {
                ulonglong2 va = hz[jj];    // .x = rows{0,1}, .y = rows{2,3}
                ulonglong2 vb = hr[jj];
                ulonglong2 vc = hh[jj];
                fma2(aZ0, va.x, Uzd[jj]); fma2(aZ1, va.y, Uzd[jj]);
                fma2(aR0, vb.x, Urd[jj]); fma2(aR1, vb.y, Urd[jj]);
                fma2(aH0, vc.x, Uhd[jj]); fma2(aH1, vc.y, Uhd[jj]);
            }
            float zf[4], rf[4], gf[4];
            unpack2(aZ0, zf[0], zf[1]); unpack2(aZ1, zf[2], zf[3]);
            unpack2(aR0, rf[0], rf[1]); unpack2(aR1, rf[2], rf[3]);
            unpack2(aH0, gf[0], gf[1]); unpack2(aH1, gf[2], gf[3]);
            #pragma unroll
            for (int r = 0; r < 4; ++r)
                if (r != s) part[s][r][u] = make_float4(zf[r], rf[r], gf[r], 0.f);
            __syncthreads();

            // phase B: finalizers (s<4) combine 8 partials, update h
            if (fin) {
                float sz = zf[s], sr = rf[s], sh = gf[s];
                #pragma unroll
                for (int q = 1; q < NSPL; ++q) {
                    int sp = (s + q) & (NSPL - 1);
                    float4 p = part[sp][s][u];
                    sz += p.x; sr += p.y; sh += p.z;
                }
                const float* Xp = Xrow + tt * (XQ * 4);
                float xz = Xp[u], xr = Xp[NU + u], xh = Xp[2 * NU + u];
                float z  = sigm(xz + sz + br0);
                float r  = sigm(xr + sr + br1);
                float th = tanh_fast(xh + r * (sh + br2));
                h = z * h + (1.f - z) * th;
                float* hb = (float*)&hm[0][0];
                hb[(0 * JPAD + u) * 4 + s] = h * rdp0;
                hb[(1 * JPAD + u) * 4 + s] = h * rdp1;
                hb[(2 * JPAD + u) * 4 + s] = h * rdp2;
            }
            __syncthreads();
        }

        // chunk boundary: refill consumed buffer with chunk c+2
        if (c + 2 < NCHUNK) issue_chunk(c + 2, buf);
        asm volatile("cp.async.wait_group 1;" ::: "memory");  // chunk c+1 ready
        __syncthreads();
    }

    // dense head: out[b] = h . Wd + bd
    if (fin) head[s][u] = h * wdu;
    __syncthreads();
    if (tid < 4) {
        float sum = bd[0];
        for (int uu = 0; uu < NU; ++uu) sum += head[tid][uu];
        out[b0 + tid] = sum;
    }
}

// ---------------- launch ----------------
extern "C" void kernel_launch(void* const* d_in, const int* in_sizes, int n_in,
                              void* d_out, int out_size)
{
    const float* inp = (const float*)d_in[0];
    const float* W   = (const float*)d_in[1];
    const float* U   = (const float*)d_in[2];
    const float* bb  = (const float*)d_in[3];
    const float* Wd  = (const float*)d_in[4];
    const float* bd  = (const float*)d_in[5];
    const float* dp  = (const float*)d_in[6];
    const float* rdp = (const float*)d_in[7];
    float* out = (float*)d_out;

    cudaFuncSetAttribute(xproj_kernel, cudaFuncAttributeMaxDynamicSharedMemorySize, SMEM_XPROJ);
    xproj_kernel<<<B_, 512, SMEM_XPROJ>>>(inp, W, bb, dp);
    scan_kernel<<<B_ / 4, 512>>>(U, bb, Wd, bd, rdp, out);
}

// round 6
// speedup vs baseline: 1.3551x; 1.3551x over previous
#include <cuda_runtime.h>
#include <cstdint>

#define B_  512
#define T_  512
#define F_  128
#define NU  50
#define NC  150   // 3*NU
#define XP  160   // padded X row (floats)

// Scratch for projected inputs X[b][t][160] (cols 150..159 unused garbage).
__device__ float g_X[(size_t)B_ * T_ * XP];

typedef unsigned long long ull;

// ---------------- packed f32x2 helpers ----------------
__device__ __forceinline__ ull dup2(float x) {
    ull r;
    asm("mov.b64 %0, {%1, %1};" : "=l"(r) : "f"(x));
    return r;
}
__device__ __forceinline__ void fma2(ull& d, ull a, ull b) {
    asm("fma.rn.f32x2 %0, %1, %2, %0;" : "+l"(d) : "l"(a), "l"(b));
}
__device__ __forceinline__ void unpack2(ull v, float& lo, float& hi) {
    asm("mov.b64 {%0, %1}, %2;" : "=f"(lo), "=f"(hi) : "l"(v));
}

__device__ __forceinline__ float sigm(float x) {
    return __fdividef(1.f, 1.f + __expf(-x));
}
__device__ __forceinline__ float tanh_fast(float x) {
    return __fdividef(2.f, 1.f + __expf(-2.f * x)) - 1.f;
}

__device__ __forceinline__ uint32_t smem_u32(const void* p) {
    uint32_t a;
    asm("{ .reg .u64 t; cvta.to.shared.u64 t, %1; cvt.u32.u64 %0, t; }"
        : "=r"(a) : "l"(p));
    return a;
}

// ---------------- Kernel 1: input projection (unchanged, best known) --------
#define RT    128            // rows (timesteps) per tile
#define AS    129            // odd stride for transposed A (conflict-free STS)
#define SM_W  (F_ * XP)      // 20480 floats
#define SM_B  (XP)           // 160
#define SM_A  (F_ * AS)      // 16512
#define SMEM_XPROJ ((SM_W + SM_B + SM_A) * 4)   // ~148.6 KB

__global__ void __launch_bounds__(512, 1) xproj_kernel(
    const float* __restrict__ inp, const float* __restrict__ W,
    const float* __restrict__ bb, const float* __restrict__ dp)
{
    extern __shared__ float sm[];
    float* Weff = sm;              // [128][160]
    float* bi_s = sm + SM_W;       // [160]
    float* A_s  = bi_s + SM_B;     // [128][129]  (k-major, transposed tile)

    const int b   = blockIdx.x;
    const int tid = threadIdx.x;

    for (int idx = tid; idx < F_ * XP; idx += 512) {
        int k = idx / XP, c = idx - k * XP;
        float w = 0.f;
        if (c < NC) w = W[k * NC + c] * dp[(c / NU) * (B_ * F_) + b * F_ + k];
        Weff[idx] = w;
    }
    for (int c = tid; c < XP; c += 512)
        bi_s[c] = (c < NC) ? bb[c] : 0.f;

    const int cx = tid & 15;
    const int ry = tid >> 4;
    const int r0 = ry * 4;
    const ull* Wv = reinterpret_cast<const ull*>(Weff);
    const ull* bv = reinterpret_cast<const ull*>(bi_s);

    for (int tile = 0; tile < T_ / RT; ++tile) {
        const int t0 = tile * RT;
        __syncthreads();
        const float* src = inp + ((size_t)b * T_ + t0) * F_;
        for (int idx = tid; idx < RT * F_; idx += 512) {
            int r = idx >> 7, k = idx & 127;
            A_s[k * AS + r] = src[idx];
        }
        __syncthreads();

        ull acc[4][5];
        #pragma unroll
        for (int i = 0; i < 4; ++i)
            #pragma unroll
            for (int j = 0; j < 5; ++j)
                acc[i][j] = bv[j * 16 + cx];

        #pragma unroll 2
        for (int k = 0; k < F_; ++k) {
            ull w[5];
            #pragma unroll
            for (int j = 0; j < 5; ++j)
                w[j] = Wv[k * (XP / 2) + j * 16 + cx];
            #pragma unroll
            for (int i = 0; i < 4; ++i) {
                ull ad = dup2(A_s[k * AS + r0 + i]);
                #pragma unroll
                for (int j = 0; j < 5; ++j)
                    fma2(acc[i][j], ad, w[j]);
            }
        }

        #pragma unroll
        for (int i = 0; i < 4; ++i) {
            ull* Xr = reinterpret_cast<ull*>(g_X + ((size_t)b * T_ + t0 + r0 + i) * XP);
            #pragma unroll
            for (int j = 0; j < 5; ++j)
                Xr[j * 16 + cx] = acc[i][j];
        }
    }
}

// ---------------- Kernel 2: recurrent scan (2 rows/CTA, 2 CTAs/SM) ----------
// 256 CTAs x 2 rows, 256 threads, occupancy 2. Thread (u = tid&63, s = tid>>6):
// 4-way split-K (JSEG=13). Both rows packed in ONE f32x2 accumulator per gate.
// hm[g][j] = ull{h0m,h1m} broadcast via LDS.64. smem float4 exchange,
// 2 barriers/step (R3 structure). X via cp.async double buffer.
#define NSPL 4
#define JSEG 13
#define JPAD 52                       // 4*JSEG; j=50,51 stay zero
#define CH   8                        // steps per chunk
#define XQ   38                       // float4 per (row,step)
#define XROWF4 (CH * XQ + 2)          // +32B pad per row
#define CHUNK_F4 (2 * CH * XQ)        // 608

__global__ void __launch_bounds__(256, 2) scan_kernel(
    const float* __restrict__ U, const float* __restrict__ bb,
    const float* __restrict__ Wd, const float* __restrict__ bd,
    const float* __restrict__ rdp, float* __restrict__ out)
{
    __shared__ ull    hm[3][JPAD];          // [gate][j] = {h_row0, h_row1}
    __shared__ float4 part[NSPL][2][64];    // [split][row][u] = {z,r,h,_}
    __shared__ float4 Xs[2 * 2 * XROWF4];   // [(buf*2+row)*XROWF4 + tt*XQ + q]
    __shared__ float  head[2][64];

    const int tid = threadIdx.x;
    const int u   = tid & 63;              // unit (active if < 50)
    const int s   = tid >> 6;              // j-quarter; s<2 also owns row s
    const int b0  = blockIdx.x * 2;
    const bool active = (u < NU);
    const bool fin    = (s < 2) && active; // finalizer for row s
    const int jbeg = s * JSEG;

    for (int idx = tid; idx < 3 * JPAD; idx += 256)
        (&hm[0][0])[idx] = 0ull;

    // U slice in registers, duplicated for 2-row-packed fma2
    ull Uzd[JSEG], Urd[JSEG], Uhd[JSEG];
    #pragma unroll
    for (int jj = 0; jj < JSEG; ++jj) {
        int j = jbeg + jj;
        float vz = 0.f, vr = 0.f, vh = 0.f;
        if (active && j < NU) {
            vz = U[j * NC + u];
            vr = U[j * NC + NU + u];
            vh = U[j * NC + 2 * NU + u];
        }
        Uzd[jj] = dup2(vz); Urd[jj] = dup2(vr); Uhd[jj] = dup2(vh);
    }

    float br0 = 0.f, br1 = 0.f, br2 = 0.f, wdu = 0.f;
    float rdp0 = 0.f, rdp1 = 0.f, rdp2 = 0.f, h = 0.f;
    if (fin) {
        br0 = bb[NC + u]; br1 = bb[NC + NU + u]; br2 = bb[NC + 2 * NU + u];
        wdu = Wd[u];
        rdp0 = rdp[0 * (B_ * NU) + (b0 + s) * NU + u];
        rdp1 = rdp[1 * (B_ * NU) + (b0 + s) * NU + u];
        rdp2 = rdp[2 * (B_ * NU) + (b0 + s) * NU + u];
    }

    // ---- cp.async chunk loader (all 256 threads) ----
    const uint32_t xs_base = smem_u32(&Xs[0]);
    auto issue_chunk = [&](int c, int buf) {
        #pragma unroll
        for (int it = 0; it < 3; ++it) {
            int lin = it * 256 + tid;
            if (lin < CHUNK_F4) {
                int r   = lin / (CH * XQ);
                int rem = lin - r * (CH * XQ);
                int tt  = rem / XQ;
                int q   = rem - tt * XQ;
                const float* g = g_X + ((size_t)(b0 + r) * T_ + c * CH + tt) * XP + q * 4;
                uint32_t dst = xs_base +
                    (uint32_t)((buf * 2 + r) * XROWF4 + tt * XQ + q) * 16u;
                asm volatile("cp.async.cg.shared.global [%0], [%1], 16;"
                             :: "r"(dst), "l"(g) : "memory");
            }
        }
        asm volatile("cp.async.commit_group;" ::: "memory");
    };

    issue_chunk(0, 0);
    issue_chunk(1, 1);
    asm volatile("cp.async.wait_group 1;" ::: "memory");   // chunk 0 ready
    __syncthreads();

    const float* XsF = reinterpret_cast<const float*>(Xs);
    const int NCHUNK = T_ / CH;   // 64
    for (int c = 0; c < NCHUNK; ++c) {
        const int buf = c & 1;
        const float* Xrow = XsF + (size_t)(buf * 2 + s) * (XROWF4 * 4);

        #pragma unroll 2
        for (int tt = 0; tt < CH; ++tt) {
            // phase A: split-K partials, both rows packed in f32x2
            ull aZ = 0, aR = 0, aH = 0;
            #pragma unroll
            for (int jj = 0; jj < JSEG; ++jj) {
                fma2(aZ, hm[0][jbeg + jj], Uzd[jj]);   // broadcast LDS.64
                fma2(aR, hm[1][jbeg + jj], Urd[jj]);
                fma2(aH, hm[2][jbeg + jj], Uhd[jj]);
            }
            float zf[2], rf[2], gf[2];
            unpack2(aZ, zf[0], zf[1]);
            unpack2(aR, rf[0], rf[1]);
            unpack2(aH, gf[0], gf[1]);
            part[s][0][u] = make_float4(zf[0], rf[0], gf[0], 0.f);
            part[s][1][u] = make_float4(zf[1], rf[1], gf[1], 0.f);
            __syncthreads();

            // phase B: finalizers (s<2) sum 4 partials for row s, update h
            if (fin) {
                float4 p0 = part[0][s][u];
                float4 p1 = part[1][s][u];
                float4 p2 = part[2][s][u];
                float4 p3 = part[3][s][u];
                float sz = (p0.x + p1.x) + (p2.x + p3.x);
                float sr = (p0.y + p1.y) + (p2.y + p3.y);
                float sh = (p0.z + p1.z) + (p2.z + p3.z);
                const float* Xp = Xrow + tt * (XQ * 4);
                float xz = Xp[u], xr = Xp[NU + u], xh = Xp[2 * NU + u];
                float z  = sigm(xz + sz + br0);
                float r  = sigm(xr + sr + br1);
                float th = tanh_fast(xh + r * (sh + br2));
                h = z * h + (1.f - z) * th;
                float* hb = (float*)&hm[0][0];
                hb[(0 * JPAD + u) * 2 + s] = h * rdp0;
                hb[(1 * JPAD + u) * 2 + s] = h * rdp1;
                hb[(2 * JPAD + u) * 2 + s] = h * rdp2;
            }
            __syncthreads();
        }

        // chunk boundary: refill consumed buffer with chunk c+2
        if (c + 2 < NCHUNK) {
            issue_chunk(c + 2, buf);
            asm volatile("cp.async.wait_group 1;" ::: "memory");  // c+1 ready
        } else {
            asm volatile("cp.async.wait_group 0;" ::: "memory");  // drain all
        }
        __syncthreads();
    }

    // dense head: out[b] = h . Wd + bd
    if (fin) head[s][u] = h * wdu;
    __syncthreads();
    if (tid < 2) {
        float sum = bd[0];
        for (int uu = 0; uu < NU; ++uu) sum += head[tid][uu];
        out[b0 + tid] = sum;
    }
}

// ---------------- launch ----------------
extern "C" void kernel_launch(void* const* d_in, const int* in_sizes, int n_in,
                              void* d_out, int out_size)
{
    const float* inp = (const float*)d_in[0];
    const float* W   = (const float*)d_in[1];
    const float* U   = (const float*)d_in[2];
    const float* bb  = (const float*)d_in[3];
    const float* Wd  = (const float*)d_in[4];
    const float* bd  = (const float*)d_in[5];
    const float* dp  = (const float*)d_in[6];
    const float* rdp = (const float*)d_in[7];
    float* out = (float*)d_out;

    cudaFuncSetAttribute(xproj_kernel, cudaFuncAttributeMaxDynamicSharedMemorySize, SMEM_XPROJ);
    xproj_kernel<<<B_, 512, SMEM_XPROJ>>>(inp, W, bb, dp);
    scan_kernel<<<B_ / 2, 256>>>(U, bb, Wd, bd, rdp, out);
}

// round 7
// speedup vs baseline: 1.3631x; 1.0059x over previous
#include <cuda_runtime.h>
#include <cstdint>

#define B_  512
#define T_  512
#define F_  128
#define NU  50
#define NC  150   // 3*NU
#define XP  160   // padded X row (floats)

// Scratch for projected inputs X[b][t][160] (cols 150..159 unused garbage).
__device__ float g_X[(size_t)B_ * T_ * XP];

typedef unsigned long long ull;

// ---------------- packed f32x2 helpers ----------------
__device__ __forceinline__ ull dup2(float x) {
    ull r;
    asm("mov.b64 %0, {%1, %1};" : "=l"(r) : "f"(x));
    return r;
}
__device__ __forceinline__ void fma2(ull& d, ull a, ull b) {
    asm("fma.rn.f32x2 %0, %1, %2, %0;" : "+l"(d) : "l"(a), "l"(b));
}
__device__ __forceinline__ void unpack2(ull v, float& lo, float& hi) {
    asm("mov.b64 {%0, %1}, %2;" : "=f"(lo), "=f"(hi) : "l"(v));
}

__device__ __forceinline__ float sigm(float x) {
    return __fdividef(1.f, 1.f + __expf(-x));
}
__device__ __forceinline__ float tanh_fast(float x) {
    return __fdividef(2.f, 1.f + __expf(-2.f * x)) - 1.f;
}

__device__ __forceinline__ uint32_t smem_u32(const void* p) {
    uint32_t a;
    asm("{ .reg .u64 t; cvta.to.shared.u64 t, %1; cvt.u32.u64 %0, t; }"
        : "=r"(a) : "l"(p));
    return a;
}

// ---------------- Kernel 1: input projection (unchanged, best known) --------
#define RT    128            // rows (timesteps) per tile
#define AS    129            // odd stride for transposed A (conflict-free STS)
#define SM_W  (F_ * XP)      // 20480 floats
#define SM_B  (XP)           // 160
#define SM_A  (F_ * AS)      // 16512
#define SMEM_XPROJ ((SM_W + SM_B + SM_A) * 4)   // ~148.6 KB

__global__ void __launch_bounds__(512, 1) xproj_kernel(
    const float* __restrict__ inp, const float* __restrict__ W,
    const float* __restrict__ bb, const float* __restrict__ dp)
{
    extern __shared__ float sm[];
    float* Weff = sm;              // [128][160]
    float* bi_s = sm + SM_W;       // [160]
    float* A_s  = bi_s + SM_B;     // [128][129]  (k-major, transposed tile)

    const int b   = blockIdx.x;
    const int tid = threadIdx.x;

    for (int idx = tid; idx < F_ * XP; idx += 512) {
        int k = idx / XP, c = idx - k * XP;
        float w = 0.f;
        if (c < NC) w = W[k * NC + c] * dp[(c / NU) * (B_ * F_) + b * F_ + k];
        Weff[idx] = w;
    }
    for (int c = tid; c < XP; c += 512)
        bi_s[c] = (c < NC) ? bb[c] : 0.f;

    const int cx = tid & 15;
    const int ry = tid >> 4;
    const int r0 = ry * 4;
    const ull* Wv = reinterpret_cast<const ull*>(Weff);
    const ull* bv = reinterpret_cast<const ull*>(bi_s);

    for (int tile = 0; tile < T_ / RT; ++tile) {
        const int t0 = tile * RT;
        __syncthreads();
        const float* src = inp + ((size_t)b * T_ + t0) * F_;
        for (int idx = tid; idx < RT * F_; idx += 512) {
            int r = idx >> 7, k = idx & 127;
            A_s[k * AS + r] = src[idx];
        }
        __syncthreads();

        ull acc[4][5];
        #pragma unroll
        for (int i = 0; i < 4; ++i)
            #pragma unroll
            for (int j = 0; j < 5; ++j)
                acc[i][j] = bv[j * 16 + cx];

        #pragma unroll 2
        for (int k = 0; k < F_; ++k) {
            ull w[5];
            #pragma unroll
            for (int j = 0; j < 5; ++j)
                w[j] = Wv[k * (XP / 2) + j * 16 + cx];
            #pragma unroll
            for (int i = 0; i < 4; ++i) {
                ull ad = dup2(A_s[k * AS + r0 + i]);
                #pragma unroll
                for (int j = 0; j < 5; ++j)
                    fma2(acc[i][j], ad, w[j]);
            }
        }

        #pragma unroll
        for (int i = 0; i < 4; ++i) {
            ull* Xr = reinterpret_cast<ull*>(g_X + ((size_t)b * T_ + t0 + r0 + i) * XP);
            #pragma unroll
            for (int j = 0; j < 5; ++j)
                Xr[j * 16 + cx] = acc[i][j];
        }
    }
}

// ---------------- Kernel 2: recurrent scan (2 rows/CTA, 2 CTAs/SM) ----------
// R6 structure frozen. ONE change: hm is laid out in 14-slot, 16B-aligned
// regions per split (slot = u + u/13) so the 13 hm broadcast loads per gate
// become 6x LDS.128 + 1x LDS.64 (21 wavefronts/step vs 39).
#define NSPL 4
#define JSEG 13
#define JREG 14                       // slots per split region (16B aligned)
#define JPAD (NSPL * JREG)            // 56
#define CH   8                        // steps per chunk
#define XQ   38                       // float4 per (row,step)
#define XROWF4 (CH * XQ + 2)          // +32B pad per row
#define CHUNK_F4 (2 * CH * XQ)        // 608

__global__ void __launch_bounds__(256, 2) scan_kernel(
    const float* __restrict__ U, const float* __restrict__ bb,
    const float* __restrict__ Wd, const float* __restrict__ bd,
    const float* __restrict__ rdp, float* __restrict__ out)
{
    __shared__ __align__(16) ull hm[3][JPAD];  // [gate][slot] = {h_row0,h_row1}
    __shared__ float4 part[NSPL][2][64];       // [split][row][u] = {z,r,h,_}
    __shared__ float4 Xs[2 * 2 * XROWF4];      // [(buf*2+row)*XROWF4 + tt*XQ + q]
    __shared__ float  head[2][64];

    const int tid = threadIdx.x;
    const int u   = tid & 63;              // unit (active if < 50)
    const int s   = tid >> 6;              // j-quarter; s<2 also owns row s
    const int b0  = blockIdx.x * 2;
    const bool active = (u < NU);
    const bool fin    = (s < 2) && active; // finalizer for row s
    const int jbeg = s * JREG;             // 16B-aligned region base
    const int slot = u + u / JSEG;         // hm slot for unit u (u<50 -> <56)

    for (int idx = tid; idx < 3 * JPAD; idx += 256)
        (&hm[0][0])[idx] = 0ull;

    // U slice in registers (13 per gate), duplicated for 2-row-packed fma2.
    // This split covers units j = s*13 + jj (jj<13); j>=50 stays zero.
    ull Uzd[JSEG], Urd[JSEG], Uhd[JSEG];
    #pragma unroll
    for (int jj = 0; jj < JSEG; ++jj) {
        int j = s * JSEG + jj;
        float vz = 0.f, vr = 0.f, vh = 0.f;
        if (active && j < NU) {
            vz = U[j * NC + u];
            vr = U[j * NC + NU + u];
            vh = U[j * NC + 2 * NU + u];
        }
        Uzd[jj] = dup2(vz); Urd[jj] = dup2(vr); Uhd[jj] = dup2(vh);
    }

    float br0 = 0.f, br1 = 0.f, br2 = 0.f, wdu = 0.f;
    float rdp0 = 0.f, rdp1 = 0.f, rdp2 = 0.f, h = 0.f;
    if (fin) {
        br0 = bb[NC + u]; br1 = bb[NC + NU + u]; br2 = bb[NC + 2 * NU + u];
        wdu = Wd[u];
        rdp0 = rdp[0 * (B_ * NU) + (b0 + s) * NU + u];
        rdp1 = rdp[1 * (B_ * NU) + (b0 + s) * NU + u];
        rdp2 = rdp[2 * (B_ * NU) + (b0 + s) * NU + u];
    }

    // ---- cp.async chunk loader (all 256 threads) ----
    const uint32_t xs_base = smem_u32(&Xs[0]);
    auto issue_chunk = [&](int c, int buf) {
        #pragma unroll
        for (int it = 0; it < 3; ++it) {
            int lin = it * 256 + tid;
            if (lin < CHUNK_F4) {
                int r   = lin / (CH * XQ);
                int rem = lin - r * (CH * XQ);
                int tt  = rem / XQ;
                int q   = rem - tt * XQ;
                const float* g = g_X + ((size_t)(b0 + r) * T_ + c * CH + tt) * XP + q * 4;
                uint32_t dst = xs_base +
                    (uint32_t)((buf * 2 + r) * XROWF4 + tt * XQ + q) * 16u;
                asm volatile("cp.async.cg.shared.global [%0], [%1], 16;"
                             :: "r"(dst), "l"(g) : "memory");
            }
        }
        asm volatile("cp.async.commit_group;" ::: "memory");
    };

    issue_chunk(0, 0);
    issue_chunk(1, 1);
    asm volatile("cp.async.wait_group 1;" ::: "memory");   // chunk 0 ready
    __syncthreads();

    const float* XsF = reinterpret_cast<const float*>(Xs);
    const int NCHUNK = T_ / CH;   // 64
    for (int c = 0; c < NCHUNK; ++c) {
        const int buf = c & 1;
        const float* Xrow = XsF + (size_t)(buf * 2 + s) * (XROWF4 * 4);

        #pragma unroll 2
        for (int tt = 0; tt < CH; ++tt) {
            // phase A: split-K partials, both rows packed in f32x2.
            // hm loads: 6 LDS.128 + 1 LDS.64 per gate.
            ull aZ = 0, aR = 0, aH = 0;
            const ulonglong2* hz2 = reinterpret_cast<const ulonglong2*>(&hm[0][jbeg]);
            const ulonglong2* hr2 = reinterpret_cast<const ulonglong2*>(&hm[1][jbeg]);
            const ulonglong2* hh2 = reinterpret_cast<const ulonglong2*>(&hm[2][jbeg]);
            #pragma unroll
            for (int p2 = 0; p2 < 6; ++p2) {
                ulonglong2 vz = hz2[p2];
                ulonglong2 vr = hr2[p2];
                ulonglong2 vh = hh2[p2];
                fma2(aZ, vz.x, Uzd[2 * p2]); fma2(aZ, vz.y, Uzd[2 * p2 + 1]);
                fma2(aR, vr.x, Urd[2 * p2]); fma2(aR, vr.y, Urd[2 * p2 + 1]);
                fma2(aH, vh.x, Uhd[2 * p2]); fma2(aH, vh.y, Uhd[2 * p2 + 1]);
            }
            fma2(aZ, hm[0][jbeg + 12], Uzd[12]);
            fma2(aR, hm[1][jbeg + 12], Urd[12]);
            fma2(aH, hm[2][jbeg + 12], Uhd[12]);

            float zf[2], rf[2], gf[2];
            unpack2(aZ, zf[0], zf[1]);
            unpack2(aR, rf[0], rf[1]);
            unpack2(aH, gf[0], gf[1]);
            part[s][0][u] = make_float4(zf[0], rf[0], gf[0], 0.f);
            part[s][1][u] = make_float4(zf[1], rf[1], gf[1], 0.f);
            __syncthreads();

            // phase B: finalizers (s<2) sum 4 partials for row s, update h
            if (fin) {
                float4 p0 = part[0][s][u];
                float4 p1 = part[1][s][u];
                float4 p2 = part[2][s][u];
                float4 p3 = part[3][s][u];
                float sz = (p0.x + p1.x) + (p2.x + p3.x);
                float sr = (p0.y + p1.y) + (p2.y + p3.y);
                float sh = (p0.z + p1.z) + (p2.z + p3.z);
                const float* Xp = Xrow + tt * (XQ * 4);
                float xz = Xp[u], xr = Xp[NU + u], xh = Xp[2 * NU + u];
                float z  = sigm(xz + sz + br0);
                float r  = sigm(xr + sr + br1);
                float th = tanh_fast(xh + r * (sh + br2));
                h = z * h + (1.f - z) * th;
                float* hb = (float*)&hm[0][0];
                hb[(0 * JPAD + slot) * 2 + s] = h * rdp0;
                hb[(1 * JPAD + slot) * 2 + s] = h * rdp1;
                hb[(2 * JPAD + slot) * 2 + s] = h * rdp2;
            }
            __syncthreads();
        }

        // chunk boundary: refill consumed buffer with chunk c+2
        if (c + 2 < NCHUNK) {
            issue_chunk(c + 2, buf);
            asm volatile("cp.async.wait_group 1;" ::: "memory");  // c+1 ready
        } else {
            asm volatile("cp.async.wait_group 0;" ::: "memory");  // drain all
        }
        __syncthreads();
    }

    // dense head: out[b] = h . Wd + bd
    if (fin) head[s][u] = h * wdu;
    __syncthreads();
    if (tid < 2) {
        float sum = bd[0];
        for (int uu = 0; uu < NU; ++uu) sum += head[tid][uu];
        out[b0 + tid] = sum;
    }
}

// ---------------- launch ----------------
extern "C" void kernel_launch(void* const* d_in, const int* in_sizes, int n_in,
                              void* d_out, int out_size)
{
    const float* inp = (const float*)d_in[0];
    const float* W   = (const float*)d_in[1];
    const float* U   = (const float*)d_in[2];
    const float* bb  = (const float*)d_in[3];
    const float* Wd  = (const float*)d_in[4];
    const float* bd  = (const float*)d_in[5];
    const float* dp  = (const float*)d_in[6];
    const float* rdp = (const float*)d_in[7];
    float* out = (float*)d_out;

    cudaFuncSetAttribute(xproj_kernel, cudaFuncAttributeMaxDynamicSharedMemorySize, SMEM_XPROJ);
    xproj_kernel<<<B_, 512, SMEM_XPROJ>>>(inp, W, bb, dp);
    scan_kernel<<<B_ / 2, 256>>>(U, bb, Wd, bd, rdp, out);
}

// round 9
// speedup vs baseline: 1.7016x; 1.2484x over previous
#include <cuda_runtime.h>
#include <cuda_bf16.h>
#include <cstdint>

#define B_  512
#define T_  512
#define F_  128
#define NU  50
#define NC  150   // 3*NU
#define XP  160   // padded X row (floats)

// Scratch for projected inputs X[b][t][160].
__device__ float g_X[(size_t)B_ * T_ * XP];

typedef unsigned long long ull;

// ---------------- packed f32x2 helpers (scan) ----------------
__device__ __forceinline__ ull dup2(float x) {
    ull r;
    asm("mov.b64 %0, {%1, %1};" : "=l"(r) : "f"(x));
    return r;
}
__device__ __forceinline__ void fma2(ull& d, ull a, ull b) {
    asm("fma.rn.f32x2 %0, %1, %2, %0;" : "+l"(d) : "l"(a), "l"(b));
}
__device__ __forceinline__ void unpack2(ull v, float& lo, float& hi) {
    asm("mov.b64 {%0, %1}, %2;" : "=f"(lo), "=f"(hi) : "l"(v));
}
__device__ __forceinline__ float sigm(float x) {
    return __fdividef(1.f, 1.f + __expf(-x));
}
__device__ __forceinline__ float tanh_fast(float x) {
    return __fdividef(2.f, 1.f + __expf(-2.f * x)) - 1.f;
}
__device__ __forceinline__ uint32_t smem_u32(const void* p) {
    uint32_t a;
    asm("{ .reg .u64 t; cvta.to.shared.u64 t, %1; cvt.u32.u64 %0, t; }"
        : "=r"(a) : "l"(p));
    return a;
}

// ================= Kernel 1: xproj via HMMA (mma.sync bf16, split-3) ========
// One CTA (256 thr, 8 warps) per batch b.
// D[M=128][N=160] = A[M][K=128] * B[N][K]^T, B[n][k] = W[k][n]*dp[n/50][b][k].
// Split bf16: D = Ah*Bh + Ah*Bl + Al*Bh (fp32 accum).
#define TM   128
#define TN   160
#define TK   128
#define LDAB 136                         // bf16 stride (272B: ldmatrix conflict-free)

// smem byte offsets
#define SX_BIAS 0                                   // 160 floats
#define SX_BH   1024                                // 160*136*2 = 43520
#define SX_BL   (SX_BH + TN * LDAB * 2)             // 44544
#define SX_AH   (SX_BL + TN * LDAB * 2)             // 88064
#define SX_AL   (SX_AH + TM * LDAB * 2)             // 122880
#define SX_TOT  (SX_AL + TM * LDAB * 2)             // 157696

__device__ __forceinline__ void ldmx4(uint32_t* r, uint32_t addr) {
    asm volatile("ldmatrix.sync.aligned.m8n8.x4.shared.b16 {%0,%1,%2,%3}, [%4];"
                 : "=r"(r[0]), "=r"(r[1]), "=r"(r[2]), "=r"(r[3]) : "r"(addr));
}
__device__ __forceinline__ void mma16816(float* c, const uint32_t* a,
                                         uint32_t b0, uint32_t b1) {
    asm volatile(
        "mma.sync.aligned.m16n8k16.row.col.f32.bf16.bf16.f32 "
        "{%0,%1,%2,%3}, {%4,%5,%6,%7}, {%8,%9}, {%0,%1,%2,%3};"
        : "+f"(c[0]), "+f"(c[1]), "+f"(c[2]), "+f"(c[3])
        : "r"(a[0]), "r"(a[1]), "r"(a[2]), "r"(a[3]), "r"(b0), "r"(b1));
}

__global__ void __launch_bounds__(256, 1) xproj_tc_kernel(
    const float* __restrict__ inp, const float* __restrict__ W,
    const float* __restrict__ bb, const float* __restrict__ dp)
{
    extern __shared__ char smx[];
    const uint32_t sb = smem_u32(smx);
    const int b   = blockIdx.x;
    const int tid = threadIdx.x;
    const int wid = tid >> 5;
    const int lid = tid & 31;

    float* bias_s = reinterpret_cast<float*>(smx + SX_BIAS);
    for (int n = tid; n < TN; n += 256)
        bias_s[n] = (n < NC) ? bb[n] : 0.f;

    // Build B = Weff^T (hi/lo bf16), rows n, cols k, stride LDAB.
    {
        __nv_bfloat162* BH = reinterpret_cast<__nv_bfloat162*>(smx + SX_BH);
        __nv_bfloat162* BL = reinterpret_cast<__nv_bfloat162*>(smx + SX_BL);
        for (int i = tid; i < TN * (TK / 2); i += 256) {
            int kp = i / TN, n = i - kp * TN;       // n-consecutive: W reads coalesced
            int k0 = 2 * kp;
            float w0 = 0.f, w1 = 0.f;
            if (n < NC) {
                int g = n / NU;
                w0 = W[k0 * NC + n]       * dp[g * (B_ * F_) + b * F_ + k0];
                w1 = W[(k0 + 1) * NC + n] * dp[g * (B_ * F_) + b * F_ + k0 + 1];
            }
            __nv_bfloat16 h0 = __float2bfloat16(w0);
            __nv_bfloat16 h1 = __float2bfloat16(w1);
            __nv_bfloat16 l0 = __float2bfloat16(w0 - __bfloat162float(h0));
            __nv_bfloat16 l1 = __float2bfloat16(w1 - __bfloat162float(h1));
            uint32_t off = (uint32_t)(n * (LDAB / 2) + kp);   // bf16x2 units
            BH[off] = __nv_bfloat162(h0, h1);
            BL[off] = __nv_bfloat162(l0, l1);
        }
    }

    // ldmatrix lane base offsets (bytes)
    const int m0 = wid * 16;
    const uint32_t a_lane = (uint32_t)(((m0 + (lid & 15)) * LDAB + ((lid >> 4) << 3)) * 2);
    const uint32_t b_lane = (uint32_t)(((((lid & 7) + ((lid >> 4) << 3)) * LDAB) +
                                        (((lid >> 3) & 1) << 3)) * 2);
    const uint32_t ah_base = sb + SX_AH + a_lane;
    const uint32_t al_base = sb + SX_AL + a_lane;
    const uint32_t bh_base = sb + SX_BH + b_lane;
    const uint32_t bl_base = sb + SX_BL + b_lane;

    for (int tile = 0; tile < T_ / TM; ++tile) {
        const int t0 = tile * TM;
        __syncthreads();   // prev tile's ldmatrix done (covers B build on tile 0)

        // Stage A tile (hi/lo bf16), rows m, cols k, stride LDAB.
        {
            __nv_bfloat162* AH = reinterpret_cast<__nv_bfloat162*>(smx + SX_AH);
            __nv_bfloat162* AL = reinterpret_cast<__nv_bfloat162*>(smx + SX_AL);
            const float2* src = reinterpret_cast<const float2*>(
                inp + ((size_t)b * T_ + t0) * F_);
            for (int i = tid; i < TM * (TK / 2); i += 256) {
                int m = i >> 6, kp = i & 63;
                float2 v = src[i];
                __nv_bfloat16 h0 = __float2bfloat16(v.x);
                __nv_bfloat16 h1 = __float2bfloat16(v.y);
                __nv_bfloat16 l0 = __float2bfloat16(v.x - __bfloat162float(h0));
                __nv_bfloat16 l1 = __float2bfloat16(v.y - __bfloat162float(h1));
                uint32_t off = (uint32_t)(m * (LDAB / 2) + kp);
                AH[off] = __nv_bfloat162(h0, h1);
                AL[off] = __nv_bfloat162(l0, l1);
            }
        }
        __syncthreads();

        // k-outer MMA loop: 8 k-steps x 10 n-pairs x (3-term split)
        float c[20][4];
        #pragma unroll
        for (int nb = 0; nb < 20; ++nb)
            #pragma unroll
            for (int q = 0; q < 4; ++q) c[nb][q] = 0.f;

        #pragma unroll
        for (int ks = 0; ks < 8; ++ks) {
            const uint32_t kb = (uint32_t)(ks * 32);   // 16 bf16 = 32 bytes
            uint32_t ah[4], al[4];
            ldmx4(ah, ah_base + kb);
            ldmx4(al, al_base + kb);
            #pragma unroll
            for (int p = 0; p < 10; ++p) {
                const uint32_t nboff = (uint32_t)(p * 16 * LDAB * 2) + kb;
                uint32_t bh[4], bl[4];
                ldmx4(bh, bh_base + nboff);
                ldmx4(bl, bl_base + nboff);
                mma16816(c[2 * p],     ah, bh[0], bh[1]);
                mma16816(c[2 * p],     ah, bl[0], bl[1]);
                mma16816(c[2 * p],     al, bh[0], bh[1]);
                mma16816(c[2 * p + 1], ah, bh[2], bh[3]);
                mma16816(c[2 * p + 1], ah, bl[2], bl[3]);
                mma16816(c[2 * p + 1], al, bh[2], bh[3]);
            }
        }

        // Epilogue: c0,c1 -> (row = m0+lid/4, col = nb*8 + 2*(lid%4)); c2,c3 -> row+8
        const int rrow = m0 + (lid >> 2);
        const int ccol = (lid & 3) * 2;
        float* o0 = g_X + ((size_t)b * T_ + t0 + rrow) * XP;
        float* o1 = o0 + 8 * XP;
        #pragma unroll
        for (int nb = 0; nb < 20; ++nb) {
            int col = nb * 8 + ccol;
            float2 bz = *reinterpret_cast<const float2*>(bias_s + col);
            float2 v0 = make_float2(c[nb][0] + bz.x, c[nb][1] + bz.y);
            float2 v1 = make_float2(c[nb][2] + bz.x, c[nb][3] + bz.y);
            *reinterpret_cast<float2*>(o0 + col) = v0;
            *reinterpret_cast<float2*>(o1 + col) = v1;
        }
    }
}

// ---------------- Kernel 2: recurrent scan (R7, unchanged) ------------------
#define NSPL 4
#define JSEG 13
#define JREG 14
#define JPAD (NSPL * JREG)            // 56
#define CH   8
#define XQ   38
#define XROWF4 (CH * XQ + 2)
#define CHUNK_F4 (2 * CH * XQ)        // 608

__global__ void __launch_bounds__(256, 2) scan_kernel(
    const float* __restrict__ U, const float* __restrict__ bb,
    const float* __restrict__ Wd, const float* __restrict__ bd,
    const float* __restrict__ rdp, float* __restrict__ out)
{
    __shared__ __align__(16) ull hm[3][JPAD];
    __shared__ float4 part[NSPL][2][64];
    __shared__ float4 Xs[2 * 2 * XROWF4];
    __shared__ float  head[2][64];

    const int tid = threadIdx.x;
    const int u   = tid & 63;
    const int s   = tid >> 6;
    const int b0  = blockIdx.x * 2;
    const bool active = (u < NU);
    const bool fin    = (s < 2) && active;
    const int jbeg = s * JREG;
    const int slot = u + u / JSEG;

    for (int idx = tid; idx < 3 * JPAD; idx += 256)
        (&hm[0][0])[idx] = 0ull;

    ull Uzd[JSEG], Urd[JSEG], Uhd[JSEG];
    #pragma unroll
    for (int jj = 0; jj < JSEG; ++jj) {
        int j = s * JSEG + jj;
        float vz = 0.f, vr = 0.f, vh = 0.f;
        if (active && j < NU) {
            vz = U[j * NC + u];
            vr = U[j * NC + NU + u];
            vh = U[j * NC + 2 * NU + u];
        }
        Uzd[jj] = dup2(vz); Urd[jj] = dup2(vr); Uhd[jj] = dup2(vh);
    }

    float br0 = 0.f, br1 = 0.f, br2 = 0.f, wdu = 0.f;
    float rdp0 = 0.f, rdp1 = 0.f, rdp2 = 0.f, h = 0.f;
    if (fin) {
        br0 = bb[NC + u]; br1 = bb[NC + NU + u]; br2 = bb[NC + 2 * NU + u];
        wdu = Wd[u];
        rdp0 = rdp[0 * (B_ * NU) + (b0 + s) * NU + u];
        rdp1 = rdp[1 * (B_ * NU) + (b0 + s) * NU + u];
        rdp2 = rdp[2 * (B_ * NU) + (b0 + s) * NU + u];
    }

    const uint32_t xs_base = smem_u32(&Xs[0]);
    auto issue_chunk = [&](int c, int buf) {
        #pragma unroll
        for (int it = 0; it < 3; ++it) {
            int lin = it * 256 + tid;
            if (lin < CHUNK_F4) {
                int r   = lin / (CH * XQ);
                int rem = lin - r * (CH * XQ);
                int tt  = rem / XQ;
                int q   = rem - tt * XQ;
                const float* g = g_X + ((size_t)(b0 + r) * T_ + c * CH + tt) * XP + q * 4;
                uint32_t dst = xs_base +
                    (uint32_t)((buf * 2 + r) * XROWF4 + tt * XQ + q) * 16u;
                asm volatile("cp.async.cg.shared.global [%0], [%1], 16;"
                             :: "r"(dst), "l"(g) : "memory");
            }
        }
        asm volatile("cp.async.commit_group;" ::: "memory");
    };

    issue_chunk(0, 0);
    issue_chunk(1, 1);
    asm volatile("cp.async.wait_group 1;" ::: "memory");
    __syncthreads();

    const float* XsF = reinterpret_cast<const float*>(Xs);
    const int NCHUNK = T_ / CH;
    for (int c = 0; c < NCHUNK; ++c) {
        const int buf = c & 1;
        const float* Xrow = XsF + (size_t)(buf * 2 + s) * (XROWF4 * 4);

        #pragma unroll 2
        for (int tt = 0; tt < CH; ++tt) {
            ull aZ = 0, aR = 0, aH = 0;
            const ulonglong2* hz2 = reinterpret_cast<const ulonglong2*>(&hm[0][jbeg]);
            const ulonglong2* hr2 = reinterpret_cast<const ulonglong2*>(&hm[1][jbeg]);
            const ulonglong2* hh2 = reinterpret_cast<const ulonglong2*>(&hm[2][jbeg]);
            #pragma unroll
            for (int p2 = 0; p2 < 6; ++p2) {
                ulonglong2 vz = hz2[p2];
                ulonglong2 vr = hr2[p2];
                ulonglong2 vh = hh2[p2];
                fma2(aZ, vz.x, Uzd[2 * p2]); fma2(aZ, vz.y, Uzd[2 * p2 + 1]);
                fma2(aR, vr.x, Urd[2 * p2]); fma2(aR, vr.y, Urd[2 * p2 + 1]);
                fma2(aH, vh.x, Uhd[2 * p2]); fma2(aH, vh.y, Uhd[2 * p2 + 1]);
            }
            fma2(aZ, hm[0][jbeg + 12], Uzd[12]);
            fma2(aR, hm[1][jbeg + 12], Urd[12]);
            fma2(aH, hm[2][jbeg + 12], Uhd[12]);

            float zf[2], rf[2], gf[2];
            unpack2(aZ, zf[0], zf[1]);
            unpack2(aR, rf[0], rf[1]);
            unpack2(aH, gf[0], gf[1]);
            part[s][0][u] = make_float4(zf[0], rf[0], gf[0], 0.f);
            part[s][1][u] = make_float4(zf[1], rf[1], gf[1], 0.f);
            __syncthreads();

            if (fin) {
                float4 p0 = part[0][s][u];
                float4 p1 = part[1][s][u];
                float4 p2 = part[2][s][u];
                float4 p3 = part[3][s][u];
                float sz = (p0.x + p1.x) + (p2.x + p3.x);
                float sr = (p0.y + p1.y) + (p2.y + p3.y);
                float sh = (p0.z + p1.z) + (p2.z + p3.z);
                const float* Xp = Xrow + tt * (XQ * 4);
                float xz = Xp[u], xr = Xp[NU + u], xh = Xp[2 * NU + u];
                float z  = sigm(xz + sz + br0);
                float r  = sigm(xr + sr + br1);
                float th = tanh_fast(xh + r * (sh + br2));
                h = z * h + (1.f - z) * th;
                float* hb = (float*)&hm[0][0];
                hb[(0 * JPAD + slot) * 2 + s] = h * rdp0;
                hb[(1 * JPAD + slot) * 2 + s] = h * rdp1;
                hb[(2 * JPAD + slot) * 2 + s] = h * rdp2;
            }
            __syncthreads();
        }

        if (c + 2 < NCHUNK) {
            issue_chunk(c + 2, buf);
            asm volatile("cp.async.wait_group 1;" ::: "memory");
        } else {
            asm volatile("cp.async.wait_group 0;" ::: "memory");
        }
        __syncthreads();
    }

    if (fin) head[s][u] = h * wdu;
    __syncthreads();
    if (tid < 2) {
        float sum = bd[0];
        for (int uu = 0; uu < NU; ++uu) sum += head[tid][uu];
        out[b0 + tid] = sum;
    }
}

// ---------------- launch ----------------
extern "C" void kernel_launch(void* const* d_in, const int* in_sizes, int n_in,
                              void* d_out, int out_size)
{
    const float* inp = (const float*)d_in[0];
    const float* W   = (const float*)d_in[1];
    const float* U   = (const float*)d_in[2];
    const float* bb  = (const float*)d_in[3];
    const float* Wd  = (const float*)d_in[4];
    const float* bd  = (const float*)d_in[5];
    const float* dp  = (const float*)d_in[6];
    const float* rdp = (const float*)d_in[7];
    float* out = (float*)d_out;

    cudaFuncSetAttribute(xproj_tc_kernel, cudaFuncAttributeMaxDynamicSharedMemorySize, SX_TOT);
    xproj_tc_kernel<<<B_, 256, SX_TOT>>>(inp, W, bb, dp);
    scan_kernel<<<B_ / 2, 256>>>(U, bb, Wd, bd, rdp, out);
}

// round 10
// speedup vs baseline: 1.8400x; 1.0813x over previous
#include <cuda_runtime.h>
#include <cuda_bf16.h>
#include <cstdint>

#define B_  512
#define T_  512
#define F_  128
#define NU  50
#define NC  150   // 3*NU
#define XP  160   // padded X row (floats)

// Scratch for projected inputs X[b][t][160].
__device__ float g_X[(size_t)B_ * T_ * XP];

typedef unsigned long long ull;

// ---------------- packed f32x2 helpers (scan) ----------------
__device__ __forceinline__ ull dup2(float x) {
    ull r;
    asm("mov.b64 %0, {%1, %1};" : "=l"(r) : "f"(x));
    return r;
}
__device__ __forceinline__ void fma2(ull& d, ull a, ull b) {
    asm("fma.rn.f32x2 %0, %1, %2, %0;" : "+l"(d) : "l"(a), "l"(b));
}
__device__ __forceinline__ void unpack2(ull v, float& lo, float& hi) {
    asm("mov.b64 {%0, %1}, %2;" : "=f"(lo), "=f"(hi) : "l"(v));
}
__device__ __forceinline__ float sigm(float x) {
    return __fdividef(1.f, 1.f + __expf(-x));
}
__device__ __forceinline__ float tanh_fast(float x) {
    return __fdividef(2.f, 1.f + __expf(-2.f * x)) - 1.f;
}
__device__ __forceinline__ uint32_t smem_u32(const void* p) {
    uint32_t a;
    asm("{ .reg .u64 t; cvta.to.shared.u64 t, %1; cvt.u32.u64 %0, t; }"
        : "=r"(a) : "l"(p));
    return a;
}

// ================= Kernel 1: xproj via HMMA, N split over 2 CTAs ============
// Grid (512, 2): CTA (b, ny) computes cols [ny*80, ny*80+80) of
// D[M=128][160] = A[M][K=128] * B^T, B[n][k] = W[k][n]*dp[n/50][b][k].
// Split bf16 3-term: D = Ah*Bh + Ah*Bl + Al*Bh (fp32 accum).
// smem 111.5KB -> 2 CTAs/SM resident (stall hiding via independent CTAs).
#define TM   128
#define TNH  80                          // N per CTA
#define TK   128
#define LDAB 136                         // bf16 stride (272B, ldmatrix-friendly)

#define SX_BIAS 0                                   // 160 floats (global cols)
#define SX_BH   1024                                // 80*136*2 = 21760
#define SX_BL   (SX_BH + TNH * LDAB * 2)            // 22784
#define SX_AH   (SX_BL + TNH * LDAB * 2)            // 44544
#define SX_AL   (SX_AH + TM * LDAB * 2)             // 79360
#define SX_TOT  (SX_AL + TM * LDAB * 2)             // 114176 (~111.5KB)

__device__ __forceinline__ void ldmx4(uint32_t* r, uint32_t addr) {
    asm volatile("ldmatrix.sync.aligned.m8n8.x4.shared.b16 {%0,%1,%2,%3}, [%4];"
                 : "=r"(r[0]), "=r"(r[1]), "=r"(r[2]), "=r"(r[3]) : "r"(addr));
}
__device__ __forceinline__ void mma16816(float* c, const uint32_t* a,
                                         uint32_t b0, uint32_t b1) {
    asm volatile(
        "mma.sync.aligned.m16n8k16.row.col.f32.bf16.bf16.f32 "
        "{%0,%1,%2,%3}, {%4,%5,%6,%7}, {%8,%9}, {%0,%1,%2,%3};"
        : "+f"(c[0]), "+f"(c[1]), "+f"(c[2]), "+f"(c[3])
        : "r"(a[0]), "r"(a[1]), "r"(a[2]), "r"(a[3]), "r"(b0), "r"(b1));
}

__global__ void __launch_bounds__(256, 2) xproj_tc_kernel(
    const float* __restrict__ inp, const float* __restrict__ W,
    const float* __restrict__ bb, const float* __restrict__ dp)
{
    extern __shared__ char smx[];
    const uint32_t sb = smem_u32(smx);
    const int b   = blockIdx.x;
    const int ny  = blockIdx.y;            // n-half: cols [ny*80, ny*80+80)
    const int n0g = ny * TNH;
    const int tid = threadIdx.x;
    const int wid = tid >> 5;
    const int lid = tid & 31;

    float* bias_s = reinterpret_cast<float*>(smx + SX_BIAS);
    for (int n = tid; n < XP; n += 256)
        bias_s[n] = (n < NC) ? bb[n] : 0.f;

    // Build B half = Weff^T rows [n0g, n0g+80) (hi/lo bf16), stride LDAB.
    {
        __nv_bfloat162* BH = reinterpret_cast<__nv_bfloat162*>(smx + SX_BH);
        __nv_bfloat162* BL = reinterpret_cast<__nv_bfloat162*>(smx + SX_BL);
        for (int i = tid; i < TNH * (TK / 2); i += 256) {
            int kp = i / TNH, n = i - kp * TNH;
            int ng = n0g + n;
            int k0 = 2 * kp;
            float w0 = 0.f, w1 = 0.f;
            if (ng < NC) {
                int g = ng / NU;
                w0 = W[k0 * NC + ng]       * dp[g * (B_ * F_) + b * F_ + k0];
                w1 = W[(k0 + 1) * NC + ng] * dp[g * (B_ * F_) + b * F_ + k0 + 1];
            }
            __nv_bfloat16 h0 = __float2bfloat16(w0);
            __nv_bfloat16 h1 = __float2bfloat16(w1);
            __nv_bfloat16 l0 = __float2bfloat16(w0 - __bfloat162float(h0));
            __nv_bfloat16 l1 = __float2bfloat16(w1 - __bfloat162float(h1));
            uint32_t off = (uint32_t)(n * (LDAB / 2) + kp);
            BH[off] = __nv_bfloat162(h0, h1);
            BL[off] = __nv_bfloat162(l0, l1);
        }
    }

    // ldmatrix lane base offsets (bytes)
    const int m0 = wid * 16;
    const uint32_t a_lane = (uint32_t)(((m0 + (lid & 15)) * LDAB + ((lid >> 4) << 3)) * 2);
    const uint32_t b_lane = (uint32_t)(((((lid & 7) + ((lid >> 4) << 3)) * LDAB) +
                                        (((lid >> 3) & 1) << 3)) * 2);
    const uint32_t ah_base = sb + SX_AH + a_lane;
    const uint32_t al_base = sb + SX_AL + a_lane;
    const uint32_t bh_base = sb + SX_BH + b_lane;
    const uint32_t bl_base = sb + SX_BL + b_lane;

    for (int tile = 0; tile < T_ / TM; ++tile) {
        const int t0 = tile * TM;
        __syncthreads();   // prev tile's ldmatrix done (covers B build on tile 0)

        // Stage A tile (hi/lo bf16), rows m, cols k, stride LDAB.
        {
            __nv_bfloat162* AH = reinterpret_cast<__nv_bfloat162*>(smx + SX_AH);
            __nv_bfloat162* AL = reinterpret_cast<__nv_bfloat162*>(smx + SX_AL);
            const float2* src = reinterpret_cast<const float2*>(
                inp + ((size_t)b * T_ + t0) * F_);
            for (int i = tid; i < TM * (TK / 2); i += 256) {
                int m = i >> 6, kp = i & 63;
                float2 v = src[i];
                __nv_bfloat16 h0 = __float2bfloat16(v.x);
                __nv_bfloat16 h1 = __float2bfloat16(v.y);
                __nv_bfloat16 l0 = __float2bfloat16(v.x - __bfloat162float(h0));
                __nv_bfloat16 l1 = __float2bfloat16(v.y - __bfloat162float(h1));
                uint32_t off = (uint32_t)(m * (LDAB / 2) + kp);
                AH[off] = __nv_bfloat162(h0, h1);
                AL[off] = __nv_bfloat162(l0, l1);
            }
        }
        __syncthreads();

        // k-outer MMA loop: 8 k-steps x 5 n-pairs x 3-term split
        float c[10][4];
        #pragma unroll
        for (int nb = 0; nb < 10; ++nb)
            #pragma unroll
            for (int q = 0; q < 4; ++q) c[nb][q] = 0.f;

        #pragma unroll
        for (int ks = 0; ks < 8; ++ks) {
            const uint32_t kb = (uint32_t)(ks * 32);   // 16 bf16 = 32 bytes
            uint32_t ah[4], al[4];
            ldmx4(ah, ah_base + kb);
            ldmx4(al, al_base + kb);
            #pragma unroll
            for (int p = 0; p < 5; ++p) {
                const uint32_t nboff = (uint32_t)(p * 16 * LDAB * 2) + kb;
                uint32_t bh[4], bl[4];
                ldmx4(bh, bh_base + nboff);
                ldmx4(bl, bl_base + nboff);
                mma16816(c[2 * p],     ah, bh[0], bh[1]);
                mma16816(c[2 * p],     ah, bl[0], bl[1]);
                mma16816(c[2 * p],     al, bh[0], bh[1]);
                mma16816(c[2 * p + 1], ah, bh[2], bh[3]);
                mma16816(c[2 * p + 1], ah, bl[2], bl[3]);
                mma16816(c[2 * p + 1], al, bh[2], bh[3]);
            }
        }

        // Epilogue: c0,c1 -> (row = m0+lid/4, col = n0g + nb*8 + 2*(lid%4)); +8 rows
        const int rrow = m0 + (lid >> 2);
        const int ccol = (lid & 3) * 2;
        float* o0 = g_X + ((size_t)b * T_ + t0 + rrow) * XP;
        float* o1 = o0 + 8 * XP;
        #pragma unroll
        for (int nb = 0; nb < 10; ++nb) {
            int col = n0g + nb * 8 + ccol;
            float2 bz = *reinterpret_cast<const float2*>(bias_s + col);
            float2 v0 = make_float2(c[nb][0] + bz.x, c[nb][1] + bz.y);
            float2 v1 = make_float2(c[nb][2] + bz.x, c[nb][3] + bz.y);
            *reinterpret_cast<float2*>(o0 + col) = v0;
            *reinterpret_cast<float2*>(o1 + col) = v1;
        }
    }
}

// ---------------- Kernel 2: recurrent scan (R7/R9, unchanged) ---------------
#define NSPL 4
#define JSEG 13
#define JREG 14
#define JPAD (NSPL * JREG)            // 56
#define CH   8
#define XQ   38
#define XROWF4 (CH * XQ + 2)
#define CHUNK_F4 (2 * CH * XQ)        // 608

__global__ void __launch_bounds__(256, 2) scan_kernel(
    const float* __restrict__ U, const float* __restrict__ bb,
    const float* __restrict__ Wd, const float* __restrict__ bd,
    const float* __restrict__ rdp, float* __restrict__ out)
{
    __shared__ __align__(16) ull hm[3][JPAD];
    __shared__ float4 part[NSPL][2][64];
    __shared__ float4 Xs[2 * 2 * XROWF4];
    __shared__ float  head[2][64];

    const int tid = threadIdx.x;
    const int u   = tid & 63;
    const int s   = tid >> 6;
    const int b0  = blockIdx.x * 2;
    const bool active = (u < NU);
    const bool fin    = (s < 2) && active;
    const int jbeg = s * JREG;
    const int slot = u + u / JSEG;

    for (int idx = tid; idx < 3 * JPAD; idx += 256)
        (&hm[0][0])[idx] = 0ull;

    ull Uzd[JSEG], Urd[JSEG], Uhd[JSEG];
    #pragma unroll
    for (int jj = 0; jj < JSEG; ++jj) {
        int j = s * JSEG + jj;
        float vz = 0.f, vr = 0.f, vh = 0.f;
        if (active && j < NU) {
            vz = U[j * NC + u];
            vr = U[j * NC + NU + u];
            vh = U[j * NC + 2 * NU + u];
        }
        Uzd[jj] = dup2(vz); Urd[jj] = dup2(vr); Uhd[jj] = dup2(vh);
    }

    float br0 = 0.f, br1 = 0.f, br2 = 0.f, wdu = 0.f;
    float rdp0 = 0.f, rdp1 = 0.f, rdp2 = 0.f, h = 0.f;
    if (fin) {
        br0 = bb[NC + u]; br1 = bb[NC + NU + u]; br2 = bb[NC + 2 * NU + u];
        wdu = Wd[u];
        rdp0 = rdp[0 * (B_ * NU) + (b0 + s) * NU + u];
        rdp1 = rdp[1 * (B_ * NU) + (b0 + s) * NU + u];
        rdp2 = rdp[2 * (B_ * NU) + (b0 + s) * NU + u];
    }

    const uint32_t xs_base = smem_u32(&Xs[0]);
    auto issue_chunk = [&](int c, int buf) {
        #pragma unroll
        for (int it = 0; it < 3; ++it) {
            int lin = it * 256 + tid;
            if (lin < CHUNK_F4) {
                int r   = lin / (CH * XQ);
                int rem = lin - r * (CH * XQ);
                int tt  = rem / XQ;
                int q   = rem - tt * XQ;
                const float* g = g_X + ((size_t)(b0 + r) * T_ + c * CH + tt) * XP + q * 4;
                uint32_t dst = xs_base +
                    (uint32_t)((buf * 2 + r) * XROWF4 + tt * XQ + q) * 16u;
                asm volatile("cp.async.cg.shared.global [%0], [%1], 16;"
                             :: "r"(dst), "l"(g) : "memory");
            }
        }
        asm volatile("cp.async.commit_group;" ::: "memory");
    };

    issue_chunk(0, 0);
    issue_chunk(1, 1);
    asm volatile("cp.async.wait_group 1;" ::: "memory");
    __syncthreads();

    const float* XsF = reinterpret_cast<const float*>(Xs);
    const int NCHUNK = T_ / CH;
    for (int c = 0; c < NCHUNK; ++c) {
        const int buf = c & 1;
        const float* Xrow = XsF + (size_t)(buf * 2 + s) * (XROWF4 * 4);

        #pragma unroll 2
        for (int tt = 0; tt < CH; ++tt) {
            ull aZ = 0, aR = 0, aH = 0;
            const ulonglong2* hz2 = reinterpret_cast<const ulonglong2*>(&hm[0][jbeg]);
            const ulonglong2* hr2 = reinterpret_cast<const ulonglong2*>(&hm[1][jbeg]);
            const ulonglong2* hh2 = reinterpret_cast<const ulonglong2*>(&hm[2][jbeg]);
            #pragma unroll
            for (int p2 = 0; p2 < 6; ++p2) {
                ulonglong2 vz = hz2[p2];
                ulonglong2 vr = hr2[p2];
                ulonglong2 vh = hh2[p2];
                fma2(aZ, vz.x, Uzd[2 * p2]); fma2(aZ, vz.y, Uzd[2 * p2 + 1]);
                fma2(aR, vr.x, Urd[2 * p2]); fma2(aR, vr.y, Urd[2 * p2 + 1]);
                fma2(aH, vh.x, Uhd[2 * p2]); fma2(aH, vh.y, Uhd[2 * p2 + 1]);
            }
            fma2(aZ, hm[0][jbeg + 12], Uzd[12]);
            fma2(aR, hm[1][jbeg + 12], Urd[12]);
            fma2(aH, hm[2][jbeg + 12], Uhd[12]);

            float zf[2], rf[2], gf[2];
            unpack2(aZ, zf[0], zf[1]);
            unpack2(aR, rf[0], rf[1]);
            unpack2(aH, gf[0], gf[1]);
            part[s][0][u] = make_float4(zf[0], rf[0], gf[0], 0.f);
            part[s][1][u] = make_float4(zf[1], rf[1], gf[1], 0.f);
            __syncthreads();

            if (fin) {
                float4 p0 = part[0][s][u];
                float4 p1 = part[1][s][u];
                float4 p2 = part[2][s][u];
                float4 p3 = part[3][s][u];
                float sz = (p0.x + p1.x) + (p2.x + p3.x);
                float sr = (p0.y + p1.y) + (p2.y + p3.y);
                float sh = (p0.z + p1.z) + (p2.z + p3.z);
                const float* Xp = Xrow + tt * (XQ * 4);
                float xz = Xp[u], xr = Xp[NU + u], xh = Xp[2 * NU + u];
                float z  = sigm(xz + sz + br0);
                float r  = sigm(xr + sr + br1);
                float th = tanh_fast(xh + r * (sh + br2));
                h = z * h + (1.f - z) * th;
                float* hb = (float*)&hm[0][0];
                hb[(0 * JPAD + slot) * 2 + s] = h * rdp0;
                hb[(1 * JPAD + slot) * 2 + s] = h * rdp1;
                hb[(2 * JPAD + slot) * 2 + s] = h * rdp2;
            }
            __syncthreads();
        }

        if (c + 2 < NCHUNK) {
            issue_chunk(c + 2, buf);
            asm volatile("cp.async.wait_group 1;" ::: "memory");
        } else {
            asm volatile("cp.async.wait_group 0;" ::: "memory");
        }
        __syncthreads();
    }

    if (fin) head[s][u] = h * wdu;
    __syncthreads();
    if (tid < 2) {
        float sum = bd[0];
        for (int uu = 0; uu < NU; ++uu) sum += head[tid][uu];
        out[b0 + tid] = sum;
    }
}

// ---------------- launch ----------------
extern "C" void kernel_launch(void* const* d_in, const int* in_sizes, int n_in,
                              void* d_out, int out_size)
{
    const float* inp = (const float*)d_in[0];
    const float* W   = (const float*)d_in[1];
    const float* U   = (const float*)d_in[2];
    const float* bb  = (const float*)d_in[3];
    const float* Wd  = (const float*)d_in[4];
    const float* bd  = (const float*)d_in[5];
    const float* dp  = (const float*)d_in[6];
    const float* rdp = (const float*)d_in[7];
    float* out = (float*)d_out;

    cudaFuncSetAttribute(xproj_tc_kernel, cudaFuncAttributeMaxDynamicSharedMemorySize, SX_TOT);
    dim3 grid(B_, 2);
    xproj_tc_kernel<<<grid, 256, SX_TOT>>>(inp, W, bb, dp);
    scan_kernel<<<B_ / 2, 256>>>(U, bb, Wd, bd, rdp, out);
}

// round 11
// speedup vs baseline: 2.0438x; 1.1108x over previous
#include <cuda_runtime.h>
#include <cuda_bf16.h>
#include <cstdint>

#define B_  512
#define T_  512
#define F_  128
#define NU  50
#define NC  150   // 3*NU
#define XP  160   // padded X row (floats)

// Scratch for projected inputs X[b][t][160].
__device__ float g_X[(size_t)B_ * T_ * XP];

typedef unsigned long long ull;

__device__ __forceinline__ float sigm(float x) {
    return __fdividef(1.f, 1.f + __expf(-x));
}
__device__ __forceinline__ float tanh_fast(float x) {
    return __fdividef(2.f, 1.f + __expf(-2.f * x)) - 1.f;
}
__device__ __forceinline__ uint32_t smem_u32(const void* p) {
    uint32_t a;
    asm("{ .reg .u64 t; cvta.to.shared.u64 t, %1; cvt.u32.u64 %0, t; }"
        : "=r"(a) : "l"(p));
    return a;
}

// ================= Kernel 1: xproj via HMMA, N split over 2 CTAs (R10) ======
#define TM   128
#define TNH  80                          // N per CTA
#define TK   128
#define LDAB 136                         // bf16 stride (272B, ldmatrix-friendly)

#define SX_BIAS 0                                   // 160 floats (global cols)
#define SX_BH   1024                                // 80*136*2 = 21760
#define SX_BL   (SX_BH + TNH * LDAB * 2)
#define SX_AH   (SX_BL + TNH * LDAB * 2)
#define SX_AL   (SX_AH + TM * LDAB * 2)
#define SX_TOT  (SX_AL + TM * LDAB * 2)             // 114176 (~111.5KB)

__device__ __forceinline__ void ldmx4(uint32_t* r, uint32_t addr) {
    asm volatile("ldmatrix.sync.aligned.m8n8.x4.shared.b16 {%0,%1,%2,%3}, [%4];"
                 : "=r"(r[0]), "=r"(r[1]), "=r"(r[2]), "=r"(r[3]) : "r"(addr));
}
__device__ __forceinline__ void mma16816(float* c, const uint32_t* a,
                                         uint32_t b0, uint32_t b1) {
    asm volatile(
        "mma.sync.aligned.m16n8k16.row.col.f32.bf16.bf16.f32 "
        "{%0,%1,%2,%3}, {%4,%5,%6,%7}, {%8,%9}, {%0,%1,%2,%3};"
        : "+f"(c[0]), "+f"(c[1]), "+f"(c[2]), "+f"(c[3])
        : "r"(a[0]), "r"(a[1]), "r"(a[2]), "r"(a[3]), "r"(b0), "r"(b1));
}

__global__ void __launch_bounds__(256, 2) xproj_tc_kernel(
    const float* __restrict__ inp, const float* __restrict__ W,
    const float* __restrict__ bb, const float* __restrict__ dp)
{
    extern __shared__ char smx[];
    const uint32_t sb = smem_u32(smx);
    const int b   = blockIdx.x;
    const int ny  = blockIdx.y;            // n-half: cols [ny*80, ny*80+80)
    const int n0g = ny * TNH;
    const int tid = threadIdx.x;
    const int wid = tid >> 5;
    const int lid = tid & 31;

    float* bias_s = reinterpret_cast<float*>(smx + SX_BIAS);
    for (int n = tid; n < XP; n += 256)
        bias_s[n] = (n < NC) ? bb[n] : 0.f;

    // Build B half = Weff^T rows [n0g, n0g+80) (hi/lo bf16), stride LDAB.
    {
        __nv_bfloat162* BH = reinterpret_cast<__nv_bfloat162*>(smx + SX_BH);
        __nv_bfloat162* BL = reinterpret_cast<__nv_bfloat162*>(smx + SX_BL);
        for (int i = tid; i < TNH * (TK / 2); i += 256) {
            int kp = i / TNH, n = i - kp * TNH;
            int ng = n0g + n;
            int k0 = 2 * kp;
            float w0 = 0.f, w1 = 0.f;
            if (ng < NC) {
                int g = ng / NU;
                w0 = W[k0 * NC + ng]       * dp[g * (B_ * F_) + b * F_ + k0];
                w1 = W[(k0 + 1) * NC + ng] * dp[g * (B_ * F_) + b * F_ + k0 + 1];
            }
            __nv_bfloat16 h0 = __float2bfloat16(w0);
            __nv_bfloat16 h1 = __float2bfloat16(w1);
            __nv_bfloat16 l0 = __float2bfloat16(w0 - __bfloat162float(h0));
            __nv_bfloat16 l1 = __float2bfloat16(w1 - __bfloat162float(h1));
            uint32_t off = (uint32_t)(n * (LDAB / 2) + kp);
            BH[off] = __nv_bfloat162(h0, h1);
            BL[off] = __nv_bfloat162(l0, l1);
        }
    }

    const int m0 = wid * 16;
    const uint32_t a_lane = (uint32_t)(((m0 + (lid & 15)) * LDAB + ((lid >> 4) << 3)) * 2);
    const uint32_t b_lane = (uint32_t)(((((lid & 7) + ((lid >> 4) << 3)) * LDAB) +
                                        (((lid >> 3) & 1) << 3)) * 2);
    const uint32_t ah_base = sb + SX_AH + a_lane;
    const uint32_t al_base = sb + SX_AL + a_lane;
    const uint32_t bh_base = sb + SX_BH + b_lane;
    const uint32_t bl_base = sb + SX_BL + b_lane;

    for (int tile = 0; tile < T_ / TM; ++tile) {
        const int t0 = tile * TM;
        __syncthreads();   // prev tile's ldmatrix done (covers B build on tile 0)

        // Stage A tile (hi/lo bf16), rows m, cols k, stride LDAB.
        {
            __nv_bfloat162* AH = reinterpret_cast<__nv_bfloat162*>(smx + SX_AH);
            __nv_bfloat162* AL = reinterpret_cast<__nv_bfloat162*>(smx + SX_AL);
            const float2* src = reinterpret_cast<const float2*>(
                inp + ((size_t)b * T_ + t0) * F_);
            for (int i = tid; i < TM * (TK / 2); i += 256) {
                int m = i >> 6, kp = i & 63;
                float2 v = src[i];
                __nv_bfloat16 h0 = __float2bfloat16(v.x);
                __nv_bfloat16 h1 = __float2bfloat16(v.y);
                __nv_bfloat16 l0 = __float2bfloat16(v.x - __bfloat162float(h0));
                __nv_bfloat16 l1 = __float2bfloat16(v.y - __bfloat162float(h1));
                uint32_t off = (uint32_t)(m * (LDAB / 2) + kp);
                AH[off] = __nv_bfloat162(h0, h1);
                AL[off] = __nv_bfloat162(l0, l1);
            }
        }
        __syncthreads();

        float c[10][4];
        #pragma unroll
        for (int nb = 0; nb < 10; ++nb)
            #pragma unroll
            for (int q = 0; q < 4; ++q) c[nb][q] = 0.f;

        #pragma unroll
        for (int ks = 0; ks < 8; ++ks) {
            const uint32_t kb = (uint32_t)(ks * 32);
            uint32_t ah[4], al[4];
            ldmx4(ah, ah_base + kb);
            ldmx4(al, al_base + kb);
            #pragma unroll
            for (int p = 0; p < 5; ++p) {
                const uint32_t nboff = (uint32_t)(p * 16 * LDAB * 2) + kb;
                uint32_t bh[4], bl[4];
                ldmx4(bh, bh_base + nboff);
                ldmx4(bl, bl_base + nboff);
                mma16816(c[2 * p],     ah, bh[0], bh[1]);
                mma16816(c[2 * p],     ah, bl[0], bl[1]);
                mma16816(c[2 * p],     al, bh[0], bh[1]);
                mma16816(c[2 * p + 1], ah, bh[2], bh[3]);
                mma16816(c[2 * p + 1], ah, bl[2], bl[3]);
                mma16816(c[2 * p + 1], al, bh[2], bh[3]);
            }
        }

        const int rrow = m0 + (lid >> 2);
        const int ccol = (lid & 3) * 2;
        float* o0 = g_X + ((size_t)b * T_ + t0 + rrow) * XP;
        float* o1 = o0 + 8 * XP;
        #pragma unroll
        for (int nb = 0; nb < 10; ++nb) {
            int col = n0g + nb * 8 + ccol;
            float2 bz = *reinterpret_cast<const float2*>(bias_s + col);
            float2 v0 = make_float2(c[nb][0] + bz.x, c[nb][1] + bz.y);
            float2 v1 = make_float2(c[nb][2] + bz.x, c[nb][3] + bz.y);
            *reinterpret_cast<float2*>(o0 + col) = v0;
            *reinterpret_cast<float2*>(o1 + col) = v1;
        }
    }
}

// ---------------- Kernel 2: recurrent scan (1 row/CTA, occ 4) ---------------
// 512 CTAs x 1 batch row, 128 threads (4 warps): u = tid&63, s = tid>>6
// (2-way split-K, JSEG=25). U in 75 scalar regs; scalar FFMA gates.
// hm float[3][64], split regions 128B-aligned (slot = j + (j>=25)*7).
// Only s=1 writes the exchange. X via cp.async double buffer. occ 4.
#define SJSEG 25
#define SCH   8                        // steps per chunk
#define SXQ   38                       // float4 per step (152 floats)
#define SXROWF4 (SCH * SXQ + 2)        // 306 (+32B pad)
#define SCHUNK_F4 (SCH * SXQ)          // 304

__global__ void __launch_bounds__(128, 4) scan_kernel(
    const float* __restrict__ U, const float* __restrict__ bb,
    const float* __restrict__ Wd, const float* __restrict__ bd,
    const float* __restrict__ rdp, float* __restrict__ out)
{
    __shared__ __align__(16) float hm[3][64];   // [gate][slot]; slot=j+(j>=25)*7
    __shared__ float4 part1[64];                // s=1 partials {z,r,h,_}
    __shared__ float4 Xs[2 * SXROWF4];          // double-buffered X chunks
    __shared__ float  head[64];

    const int tid = threadIdx.x;
    const int u   = tid & 63;               // unit (active if < 50)
    const int s   = tid >> 6;               // j-half
    const int b   = blockIdx.x;             // one batch row
    const bool active = (u < NU);
    const bool fin    = (s == 0) && active; // finalizer for unit u
    const int rbase = s * 32;               // hm region base (128B aligned)
    const int slot  = u + ((u >= SJSEG) ? 7 : 0);

    for (int idx = tid; idx < 3 * 64; idx += 128)
        (&hm[0][0])[idx] = 0.f;

    // U slice in scalar registers: j = s*25 + jj
    float Uz[SJSEG], Ur[SJSEG], Uh[SJSEG];
    #pragma unroll
    for (int jj = 0; jj < SJSEG; ++jj) {
        int j = s * SJSEG + jj;
        float vz = 0.f, vr = 0.f, vh = 0.f;
        if (active) {
            vz = U[j * NC + u];
            vr = U[j * NC + NU + u];
            vh = U[j * NC + 2 * NU + u];
        }
        Uz[jj] = vz; Ur[jj] = vr; Uh[jj] = vh;
    }

    float br0 = 0.f, br1 = 0.f, br2 = 0.f, wdu = 0.f;
    float rdp0 = 0.f, rdp1 = 0.f, rdp2 = 0.f, h = 0.f;
    if (fin) {
        br0 = bb[NC + u]; br1 = bb[NC + NU + u]; br2 = bb[NC + 2 * NU + u];
        wdu = Wd[u];
        rdp0 = rdp[0 * (B_ * NU) + b * NU + u];
        rdp1 = rdp[1 * (B_ * NU) + b * NU + u];
        rdp2 = rdp[2 * (B_ * NU) + b * NU + u];
    }

    // ---- cp.async chunk loader (all 128 threads) ----
    const uint32_t xs_base = smem_u32(&Xs[0]);
    auto issue_chunk = [&](int c, int buf) {
        #pragma unroll
        for (int it = 0; it < 3; ++it) {
            int lin = it * 128 + tid;
            if (lin < SCHUNK_F4) {
                int tt = lin / SXQ;
                int q  = lin - tt * SXQ;
                const float* g = g_X + ((size_t)b * T_ + c * SCH + tt) * XP + q * 4;
                uint32_t dst = xs_base +
                    (uint32_t)(buf * SXROWF4 + tt * SXQ + q) * 16u;
                asm volatile("cp.async.cg.shared.global [%0], [%1], 16;"
                             :: "r"(dst), "l"(g) : "memory");
            }
        }
        asm volatile("cp.async.commit_group;" ::: "memory");
    };

    issue_chunk(0, 0);
    issue_chunk(1, 1);
    asm volatile("cp.async.wait_group 1;" ::: "memory");   // chunk 0 ready
    __syncthreads();

    const float* XsF = reinterpret_cast<const float*>(Xs);
    const int NCHUNK = T_ / SCH;   // 64
    for (int c = 0; c < NCHUNK; ++c) {
        const int buf = c & 1;
        const float* Xrow = XsF + (size_t)buf * (SXROWF4 * 4);

        #pragma unroll 2
        for (int tt = 0; tt < SCH; ++tt) {
            // phase A: split-K partials, scalar FFMA, broadcast LDS.128
            float az = 0.f, ar = 0.f, ah = 0.f;
            const float4* hz4 = reinterpret_cast<const float4*>(&hm[0][rbase]);
            const float4* hr4 = reinterpret_cast<const float4*>(&hm[1][rbase]);
            const float4* hh4 = reinterpret_cast<const float4*>(&hm[2][rbase]);
            #pragma unroll
            for (int i = 0; i < 6; ++i) {
                float4 vz = hz4[i], vr = hr4[i], vh = hh4[i];
                az = fmaf(vz.x, Uz[4*i+0], az); ar = fmaf(vr.x, Ur[4*i+0], ar);
                ah = fmaf(vh.x, Uh[4*i+0], ah);
                az = fmaf(vz.y, Uz[4*i+1], az); ar = fmaf(vr.y, Ur[4*i+1], ar);
                ah = fmaf(vh.y, Uh[4*i+1], ah);
                az = fmaf(vz.z, Uz[4*i+2], az); ar = fmaf(vr.z, Ur[4*i+2], ar);
                ah = fmaf(vh.z, Uh[4*i+2], ah);
                az = fmaf(vz.w, Uz[4*i+3], az); ar = fmaf(vr.w, Ur[4*i+3], ar);
                ah = fmaf(vh.w, Uh[4*i+3], ah);
            }
            az = fmaf(hm[0][rbase + 24], Uz[24], az);
            ar = fmaf(hm[1][rbase + 24], Ur[24], ar);
            ah = fmaf(hm[2][rbase + 24], Uh[24], ah);

            if (s) part1[u] = make_float4(az, ar, ah, 0.f);
            __syncthreads();

            // phase B: finalizers combine 2 partials, update h, broadcast
            if (fin) {
                float4 p = part1[u];
                float sz = az + p.x, sr = ar + p.y, sh = ah + p.z;
                const float* Xp = Xrow + tt * (SXQ * 4);
                float xz = Xp[u], xr = Xp[NU + u], xh = Xp[2 * NU + u];
                float z  = sigm(xz + sz + br0);
                float r  = sigm(xr + sr + br1);
                float th = tanh_fast(xh + r * (sh + br2));
                h = z * h + (1.f - z) * th;
                hm[0][slot] = h * rdp0;
                hm[1][slot] = h * rdp1;
                hm[2][slot] = h * rdp2;
            }
            __syncthreads();
        }

        // chunk boundary: refill consumed buffer with chunk c+2
        if (c + 2 < NCHUNK) {
            issue_chunk(c + 2, buf);
            asm volatile("cp.async.wait_group 1;" ::: "memory");  // c+1 ready
        } else {
            asm volatile("cp.async.wait_group 0;" ::: "memory");  // drain all
        }
        __syncthreads();
    }

    // dense head: out[b] = h . Wd + bd
    if (fin) head[u] = h * wdu;
    __syncthreads();
    if (tid == 0) {
        float sum = bd[0];
        for (int uu = 0; uu < NU; ++uu) sum += head[uu];
        out[b] = sum;
    }
}

// ---------------- launch ----------------
extern "C" void kernel_launch(void* const* d_in, const int* in_sizes, int n_in,
                              void* d_out, int out_size)
{
    const float* inp = (const float*)d_in[0];
    const float* W   = (const float*)d_in[1];
    const float* U   = (const float*)d_in[2];
    const float* bb  = (const float*)d_in[3];
    const float* Wd  = (const float*)d_in[4];
    const float* bd  = (const float*)d_in[5];
    const float* dp  = (const float*)d_in[6];
    const float* rdp = (const float*)d_in[7];
    float* out = (float*)d_out;

    cudaFuncSetAttribute(xproj_tc_kernel, cudaFuncAttributeMaxDynamicSharedMemorySize, SX_TOT);
    dim3 grid(B_, 2);
    xproj_tc_kernel<<<grid, 256, SX_TOT>>>(inp, W, bb, dp);
    scan_kernel<<<B_, 128>>>(U, bb, Wd, bd, rdp, out);
}